// round 4
// baseline (speedup 1.0000x reference)
#include <cuda_runtime.h>
#include <cuda_fp16.h>
#include <cstdint>

#define NN 64
#define HH 512
#define TB 64
#define PIT 136    // pitch in halves for all [64 x (64hi|64lo)] tiles

// shared memory byte offsets
#define OFF_XN    0          // 64 floats
#define OFF_EPI   256        // 512 * float4 = 8192
#define OFF_X     8448       // 64*136*2 = 17408  (X hi|lo; later A3)
#define OFF_W13   25856      // W1 / W3 chunk
#define OFF_W2    43264      // W2 chunk; later reduce buffer
#define OFF_A2    60672      // relu(H1) chunk
#define SMEM_BYTES 78080

// ---------------------------------------------------------------- helpers
__device__ __forceinline__ void mma16816(float c[4],
                                         uint32_t a0, uint32_t a1, uint32_t a2, uint32_t a3,
                                         uint32_t b0, uint32_t b1) {
    asm volatile(
        "mma.sync.aligned.m16n8k16.row.col.f32.f16.f16.f32 "
        "{%0,%1,%2,%3}, {%4,%5,%6,%7}, {%8,%9}, {%0,%1,%2,%3};\n"
        : "+f"(c[0]), "+f"(c[1]), "+f"(c[2]), "+f"(c[3])
        : "r"(a0), "r"(a1), "r"(a2), "r"(a3), "r"(b0), "r"(b1));
}

__device__ __forceinline__ void split_store2(__half* hiP, __half* loP, float a, float b) {
    __half ha = __float2half_rn(a), hb = __float2half_rn(b);
    __half la = __float2half_rn(a - __half2float(ha));
    __half lb = __float2half_rn(b - __half2float(hb));
    *(__half2*)hiP = __halves2half2(ha, hb);
    *(__half2*)loP = __halves2half2(la, lb);
}
__device__ __forceinline__ void split_store4(__half* hiP, __half* loP, float4 v) {
    split_store2(hiP,     loP,     v.x, v.y);
    split_store2(hiP + 2, loP + 2, v.z, v.w);
}

// K=64 hi|lo GEMM with 3 compensation passes (hi*hi + lo*hi + hi*lo).
// Warp computes C[16 rows x 32 cols] starting at (rbase, cbase).
__device__ __forceinline__ void gemm64(const __half* At, const __half* Wt,
                                       int rbase, int cbase, int g, int tg,
                                       float acc[4][4]) {
    const int pa[3] = {0, 64, 0};
    const int pb[3] = {0, 0, 64};
    #pragma unroll
    for (int p = 0; p < 3; ++p) {
        #pragma unroll
        for (int ks = 0; ks < 4; ++ks) {
            const int kA = pa[p] + ks * 16 + tg * 2;
            const int kB = pb[p] + ks * 16 + tg * 2;
            const __half* ab = At + (rbase + g) * PIT + kA;
            uint32_t a0 = *(const uint32_t*)(ab);
            uint32_t a1 = *(const uint32_t*)(ab + 8 * PIT);
            uint32_t a2 = *(const uint32_t*)(ab + 8);
            uint32_t a3 = *(const uint32_t*)(ab + 8 * PIT + 8);
            #pragma unroll
            for (int j = 0; j < 4; ++j) {
                const __half* bb = Wt + (cbase + j * 8 + g) * PIT + kB;
                uint32_t b0 = *(const uint32_t*)(bb);
                uint32_t b1 = *(const uint32_t*)(bb + 8);
                mma16816(acc[j], a0, a1, a2, a3, b0, b1);
            }
        }
    }
}

// ---------------------------------------------------------------- kernel
__global__ __launch_bounds__(256, 2)
void ctp_hmma2_kernel(const float* __restrict__ x,
                      const float* __restrict__ W1,
                      const float* __restrict__ W2,
                      const float* __restrict__ W3,
                      const float* __restrict__ b3,
                      const float* __restrict__ W4,
                      const float* __restrict__ b4,
                      float* __restrict__ out)
{
    extern __shared__ char sm[];
    float*  sXn  = (float*)(sm + OFF_XN);
    float4* sEpi = (float4*)(sm + OFF_EPI);
    __half* Xt   = (__half*)(sm + OFF_X);
    __half* W13t = (__half*)(sm + OFF_W13);
    __half* W2t  = (__half*)(sm + OFF_W2);
    __half* A2t  = (__half*)(sm + OFF_A2);

    const int tid  = threadIdx.x;
    const int wid  = tid >> 5;
    const int lane = tid & 31;
    const int g    = lane >> 2;
    const int tg   = lane & 3;
    const int rb   = (wid & 3) * 16;   // warp's 16-row batch group
    const int cb   = (wid >> 2) * 32;  // warp's 32-col half
    const int hh   = wid >> 2;
    const int n    = blockIdx.x;
    const int r0   = blockIdx.y * TB;

    // ---- prologue: X tile (col n zeroed, xn captured) + epilogue vectors ----
    {
        const int row = tid >> 2;
        const int qd  = (tid & 3) * 16;
        const float* xr = x + (r0 + row) * NN + qd;
        #pragma unroll
        for (int i = 0; i < 4; ++i) {
            const int c = qd + i * 4;
            float4 v = *(const float4*)(xr + i * 4);
            if (n >= c && n < c + 4) {
                float vv[4] = {v.x, v.y, v.z, v.w};
                sXn[row] = vv[n - c];
                vv[n - c] = 0.0f;
                v = make_float4(vv[0], vv[1], vv[2], vv[3]);
            }
            split_store4(Xt + row * PIT + c, Xt + row * PIT + 64 + c, v);
        }
    }
    for (int idx = tid; idx < HH; idx += 256)
        sEpi[idx] = make_float4(W3[(n * HH + idx) * 128 + 64 + n],
                                b3[n * HH + idx],
                                W4[n * HH + idx], 0.0f);
    const float b4n = b4[n];

    float acc2[4][4] = {};   // D2 [64b x 64m] warp slice, persistent

    // =================== Stages 1+2 over 8 H-chunks of 64 ===================
    for (int hc = 0; hc < 8; ++hc) {
        __syncthreads();   // previous chunk's consumers done
        // W1 chunk [64h x 64k]
        for (int idx = tid; idx < 1024; idx += 256) {
            const int row = idx >> 4, q = (idx & 15) * 4;
            float4 v = *(const float4*)(W1 + n * (HH * NN) + (hc * 64 + row) * NN + q);
            split_store4(W13t + row * PIT + q, W13t + row * PIT + 64 + q, v);
        }
        // W2 chunk [64m x 64k]
        for (int idx = tid; idx < 1024; idx += 256) {
            const int m = idx >> 4, q = (idx & 15) * 4;
            float4 v = *(const float4*)(W2 + n * (NN * HH) + m * HH + hc * 64 + q);
            split_store4(W2t + m * PIT + q, W2t + m * PIT + 64 + q, v);
        }
        __syncthreads();

        // stage 1: D1 chunk [64b x 64h] = X @ W1c^T
        float acc1[4][4] = {};
        gemm64(Xt, W13t, rb, cb, g, tg, acc1);

        // relu + split-store into A2
        #pragma unroll
        for (int j = 0; j < 4; ++j) {
            const int c = cb + j * 8 + tg * 2;
            split_store2(A2t + (rb + g) * PIT + c,     A2t + (rb + g) * PIT + 64 + c,
                         fmaxf(acc1[j][0], 0.f), fmaxf(acc1[j][1], 0.f));
            split_store2(A2t + (rb + 8 + g) * PIT + c, A2t + (rb + 8 + g) * PIT + 64 + c,
                         fmaxf(acc1[j][2], 0.f), fmaxf(acc1[j][3], 0.f));
        }
        __syncthreads();

        // stage 2 partial: D2 += A2c @ W2c^T
        gemm64(A2t, W2t, rb, cb, g, tg, acc2);
    }

    // ---- A3 = relu(D2) -> hi/lo into X buffer (X dead after stage 1) ----
    #pragma unroll
    for (int j = 0; j < 4; ++j) {
        const int c = cb + j * 8 + tg * 2;
        split_store2(Xt + (rb + g) * PIT + c,     Xt + (rb + g) * PIT + 64 + c,
                     fmaxf(acc2[j][0], 0.f), fmaxf(acc2[j][1], 0.f));
        split_store2(Xt + (rb + 8 + g) * PIT + c, Xt + (rb + 8 + g) * PIT + 64 + c,
                     fmaxf(acc2[j][2], 0.f), fmaxf(acc2[j][3], 0.f));
    }

    const float xn0 = sXn[rb + g];
    const float xn1 = sXn[rb + 8 + g];

    // =================== Stage 3 over 8 H-chunks, fused epilogue ===================
    float rowSum[2] = {};
    for (int hc = 0; hc < 8; ++hc) {
        __syncthreads();   // prior W13 readers done; (first iter: A3 stores ordered)
        for (int idx = tid; idx < 1024; idx += 256) {
            const int row = idx >> 4, q = (idx & 15) * 4;
            float4 v = *(const float4*)(W3 + n * (HH * 128) + (hc * 64 + row) * 128 + q);
            split_store4(W13t + row * PIT + q, W13t + row * PIT + 64 + q, v);
        }
        __syncthreads();

        float acc3[4][4] = {};
        gemm64(Xt, W13t, rb, cb, g, tg, acc3);

        // z = d3 + xn*w3col + b3 ; rowSum += relu(z)*w4
        #pragma unroll
        for (int j = 0; j < 4; ++j) {
            const int colb = hc * 64 + cb + j * 8 + tg * 2;
            const float4 e0 = sEpi[colb];
            const float4 e1 = sEpi[colb + 1];
            rowSum[0] += fmaxf(acc3[j][0] + xn0 * e0.x + e0.y, 0.f) * e0.z;
            rowSum[0] += fmaxf(acc3[j][1] + xn0 * e1.x + e1.y, 0.f) * e1.z;
            rowSum[1] += fmaxf(acc3[j][2] + xn1 * e0.x + e0.y, 0.f) * e0.z;
            rowSum[1] += fmaxf(acc3[j][3] + xn1 * e1.x + e1.y, 0.f) * e1.z;
        }
    }

    // reduce across the 4 threads of each group, then across the two column halves
    __syncthreads();
    float* Pred = (float*)(sm + OFF_W2);   // [2][64]
    {
        float v0 = rowSum[0], v1 = rowSum[1];
        v0 += __shfl_xor_sync(0xffffffffu, v0, 1);
        v0 += __shfl_xor_sync(0xffffffffu, v0, 2);
        v1 += __shfl_xor_sync(0xffffffffu, v1, 1);
        v1 += __shfl_xor_sync(0xffffffffu, v1, 2);
        if (tg == 0) {
            Pred[hh * 64 + rb + g]     = v0;
            Pred[hh * 64 + rb + 8 + g] = v1;
        }
    }
    __syncthreads();
    if (tid < 64) {
        const float tot = Pred[tid] + Pred[64 + tid];
        out[(r0 + tid) * NN + n] = fmaxf(tot + b4n, 0.0f);
    }
}

extern "C" void kernel_launch(void* const* d_in, const int* in_sizes, int n_in,
                              void* d_out, int out_size)
{
    const float* x  = (const float*)d_in[0];
    const float* W1 = (const float*)d_in[1];
    const float* W2 = (const float*)d_in[2];
    const float* W3 = (const float*)d_in[3];
    const float* b3 = (const float*)d_in[4];
    const float* W4 = (const float*)d_in[5];
    const float* b4 = (const float*)d_in[6];
    float* out = (float*)d_out;

    cudaFuncSetAttribute(ctp_hmma2_kernel,
                         cudaFuncAttributeMaxDynamicSharedMemorySize, SMEM_BYTES);

    dim3 grid(NN, 1024 / TB);   // (64 nodes, 16 batch tiles of 64)
    ctp_hmma2_kernel<<<grid, 256, SMEM_BYTES>>>(x, W1, W2, W3, b3, W4, b4, out);
}